// round 17
// baseline (speedup 1.0000x reference)
#include <cuda_runtime.h>
#include <cuda_fp16.h>
#include <math.h>
#include <stdint.h>

#define SEQ   2048
#define EMB   2048
#define DIM   2048
#define BATCH 4

typedef __half h16;

// ---------------------------------------------------------------------------
// Device scratch (no cudaMalloc allowed anywhere)
// ---------------------------------------------------------------------------
__device__ h16 g_xhi[(size_t)BATCH * SEQ * EMB];
__device__ h16 g_Wqhi[(size_t)DIM * EMB];
__device__ h16 g_Wkhi[(size_t)DIM * EMB];
__device__ h16 g_Wvhi[(size_t)DIM * EMB];
__device__ h16 g_Qhi[(size_t)BATCH * SEQ * DIM];
__device__ h16 g_Khi[(size_t)BATCH * SEQ * DIM];
__device__ h16 g_Vthi[(size_t)BATCH * DIM * SEQ];   // V^T per batch
__device__ float g_S [(size_t)BATCH * SEQ * SEQ];
__device__ h16 g_Phi[(size_t)BATCH * SEQ * SEQ];

// ---------------------------------------------------------------------------
// PTX helpers (sm_80-level PTX only; no arch-suffixed instructions)
// ---------------------------------------------------------------------------
__device__ __forceinline__ uint32_t smem_u32(const void* p) {
    uint32_t a;
    asm("{ .reg .u64 t; cvta.to.shared.u64 t, %1; cvt.u32.u64 %0, t; }"
        : "=r"(a) : "l"(p));
    return a;
}

__device__ __forceinline__ void cp16(uint32_t dst, const void* src) {
    asm volatile("cp.async.cg.shared.global [%0], [%1], 16;" :: "r"(dst), "l"(src));
}
__device__ __forceinline__ void cp_commit() {
    asm volatile("cp.async.commit_group;" ::: "memory");
}
template<int N> __device__ __forceinline__ void cp_wait() {
    asm volatile("cp.async.wait_group %0;" :: "n"(N) : "memory");
}

__device__ __forceinline__ void ldm4(uint32_t& r0, uint32_t& r1, uint32_t& r2,
                                     uint32_t& r3, uint32_t addr) {
    asm volatile("ldmatrix.sync.aligned.m8n8.x4.shared.b16 {%0,%1,%2,%3}, [%4];"
                 : "=r"(r0), "=r"(r1), "=r"(r2), "=r"(r3) : "r"(addr));
}

__device__ __forceinline__ void mma16816(float* c, const uint32_t* a,
                                         uint32_t b0, uint32_t b1) {
    asm volatile(
        "mma.sync.aligned.m16n8k16.row.col.f32.f16.f16.f32 "
        "{%0,%1,%2,%3}, {%4,%5,%6,%7}, {%8,%9}, {%0,%1,%2,%3};"
        : "+f"(c[0]), "+f"(c[1]), "+f"(c[2]), "+f"(c[3])
        : "r"(a[0]), "r"(a[1]), "r"(a[2]), "r"(a[3]), "r"(b0), "r"(b1));
}

// ---------------------------------------------------------------------------
// Tiling constants. CTA tile 128x128, 128 threads = 4 warps, warp tile 64x64
// (2x2 warp grid) — halves LDSM fragment re-read traffic vs 32x64.
// ---------------------------------------------------------------------------
#define ROWB 80                     // smem row stride bytes (32 h16 = 64B data + 16B pad)
#define TILEB (128 * ROWB)          // 10240 B per 128x32 tile
#define STG   (2 * TILEB)           // A, B per stage
#define NSTAGE 5                    // ring depth (single-barrier-per-chunk safe)
static constexpr unsigned SMEM_BYTES = NSTAGE * STG;   // 102400; >= 34816 epilogue stage

// ---------------------------------------------------------------------------
// Shared GEMM mainloop (C = A @ B^T, K-major ld 2048), 128 threads.
// 5-deep cp.async ring, prefetch distance 3, one barrier per 32-K chunk.
// Warp tile 64x64: acc[4][8][4] (128 regs), frags 64 regs.
// Per-accumulator MMA order: half0 then half1 (bitwise-stable numerics).
// ---------------------------------------------------------------------------
__device__ __forceinline__ void gemm_mainloop(
    const h16* __restrict__ Ah, const h16* __restrict__ Bh,
    uint32_t sbase, int nk, int tid, int lane, int warp_m, int warp_n,
    float acc[4][8][4])
{
    // loader: thread t owns row t of both tiles; 4 x 16B chunks each
    auto load_stage = [&](int kc) {
        const uint32_t sd = sbase + (uint32_t)(kc % NSTAGE) * STG;
        const size_t goff = (size_t)kc * 32;
        const char* pa = (const char*)(Ah + goff) + (size_t)tid * 4096;
        const char* pb = (const char*)(Bh + goff) + (size_t)tid * 4096;
        const uint32_t so = (uint32_t)tid * ROWB;
#pragma unroll
        for (int c = 0; c < 4; ++c) {
            cp16(sd + so + c * 16,         pa + c * 16);
            cp16(sd + TILEB + so + c * 16, pb + c * 16);
        }
        cp_commit();
    };

    load_stage(0);
    load_stage(1);
    load_stage(2);

    const uint32_t lrh = (uint32_t)(lane & 15) * ROWB + (uint32_t)(lane >> 4) * 16;
    const uint32_t aoff = (uint32_t)(warp_m * 64) * ROWB + lrh;
    const uint32_t boff = (uint32_t)TILEB + (uint32_t)(warp_n * 64) * ROWB + lrh;

    for (int s = 0; s < nk; ++s) {
        if (s + 3 < nk) load_stage(s + 3);
        else            cp_commit();          // empty group keeps wait count aligned
        cp_wait<3>();
        __syncthreads();

        const uint32_t sd = sbase + (uint32_t)(s % NSTAGE) * STG;

        // ---- all 16 LDSM for the chunk, back-to-back ----
        uint32_t ah[2][4][4];     // [half][mt][reg]
        uint32_t bf[2][4][4];     // [half][g][reg]
#pragma unroll
        for (int half = 0; half < 2; ++half)
#pragma unroll
            for (int mt = 0; mt < 4; ++mt) {
                const uint32_t ro = sd + aoff + (uint32_t)(mt * 16) * ROWB
                                  + (uint32_t)half * 32;
                ldm4(ah[half][mt][0], ah[half][mt][1],
                     ah[half][mt][2], ah[half][mt][3], ro);
            }
#pragma unroll
        for (int half = 0; half < 2; ++half)
#pragma unroll
            for (int g = 0; g < 4; ++g) {
                const uint32_t ro = sd + boff + (uint32_t)(g * 16) * ROWB
                                  + (uint32_t)half * 32;
                ldm4(bf[half][g][0], bf[half][g][1],
                     bf[half][g][2], bf[half][g][3], ro);
            }

        // ---- 64 HMMA per warp per chunk ----
#pragma unroll
        for (int half = 0; half < 2; ++half)
#pragma unroll
            for (int mt = 0; mt < 4; ++mt)
#pragma unroll
                for (int nt = 0; nt < 8; ++nt) {
                    const int g = nt >> 1, o = nt & 1;
                    mma16816(acc[mt][nt], ah[half][mt],
                             bf[half][g][o], bf[half][g][2 + o]);
                }
    }
    __syncthreads();   // protect smem reuse by epilogue staging
}

// ---------------------------------------------------------------------------
// QKV projection kernel. z = blockIdx.z + zbase selects W / output / mode.
//   z=0: Q row-major, z=1: K row-major, z=2: V transposed (smem-staged)
// ---------------------------------------------------------------------------
__global__ __launch_bounds__(128, 2)
void proj_gemm(const h16* __restrict__ x,
               const h16* __restrict__ wq, const h16* __restrict__ wk,
               const h16* __restrict__ wv,
               h16* __restrict__ qo, h16* __restrict__ ko, h16* __restrict__ vto,
               int zbase)
{
    const int bx = blockIdx.x, by = blockIdx.y;
    const int z  = (int)blockIdx.z + zbase;

    extern __shared__ char smem[];
    const uint32_t sbase = smem_u32(smem);

    const int tid    = threadIdx.x;
    const int wid    = tid >> 5;
    const int lane   = tid & 31;
    const int warp_m = wid & 1;           // 2 x 64 rows
    const int warp_n = wid >> 1;          // 2 x 64 cols

    const h16* Bw = (z == 0) ? wq : (z == 1) ? wk : wv;
    h16* out = (z == 0) ? qo : (z == 1) ? ko : vto;

    const h16* Ah = x  + (size_t)(by * 128) * 2048;
    const h16* Bh = Bw + (size_t)(bx * 128) * 2048;

    float acc[4][8][4] = {};
    gemm_mainloop(Ah, Bh, sbase, 64, tid, lane, warp_m, warp_n, acc);

    const int tq = lane >> 2;
    const int tr = lane & 3;

    if (z == 2) {
        // stage tile in smem, coalesced transposed write (V^T)
#pragma unroll
        for (int mt = 0; mt < 4; ++mt)
#pragma unroll
            for (int nt = 0; nt < 8; ++nt) {
                const int ml = warp_m * 64 + mt * 16 + tq;
                const int nl = warp_n * 64 + nt * 8 + tr * 2;
#pragma unroll
                for (int h = 0; h < 2; ++h) {
                    const float c0 = acc[mt][nt][h * 2 + 0];
                    const float c1 = acc[mt][nt][h * 2 + 1];
                    const uint32_t so = (uint32_t)(ml + h * 8) * 272 + (uint32_t)nl * 2;
                    *(__half2*)(smem + so) =
                        __halves2half2(__float2half_rn(c0), __float2half_rn(c1));
                }
            }
        __syncthreads();
        const int b   = by >> 4;
        const int st0 = (by & 15) * 128;
        const int nl  = tid;               // 0..127 (output row = dim index)
        const size_t obase = ((size_t)b * 2048 + bx * 128 + nl) * 2048 + st0;
#pragma unroll 4
        for (int j = 0; j < 128; j += 2) {
            const uint32_t s0 = (uint32_t)j * 272 + (uint32_t)nl * 2;
            h16 a0 = *(const h16*)(smem + s0);
            h16 a1 = *(const h16*)(smem + s0 + 272);
            *(__half2*)(out + obase + j) = __halves2half2(a0, a1);
        }
        return;
    }

#pragma unroll
    for (int mt = 0; mt < 4; ++mt)
#pragma unroll
        for (int nt = 0; nt < 8; ++nt) {
            const int gm = by * 128 + warp_m * 64 + mt * 16 + tq;
            const int gn = bx * 128 + warp_n * 64 + nt * 8 + tr * 2;
#pragma unroll
            for (int h = 0; h < 2; ++h) {
                const size_t o = (size_t)(gm + h * 8) * 2048 + gn;
                *(__half2*)(out + o) = __halves2half2(
                    __float2half_rn(acc[mt][nt][h * 2 + 0]),
                    __float2half_rn(acc[mt][nt][h * 2 + 1]));
            }
        }
}

// ---------------------------------------------------------------------------
// Attention GEMMs. Heavy-first remap: by = 15 - blockIdx.y.
//   MODE 2: scores -> fp32 * scale, causal tile skip
//   MODE 3: attn @ V^T -> fp32, causal K bound
// ---------------------------------------------------------------------------
template<int MODE>
__global__ __launch_bounds__(128, 2)
void attn_gemm(const h16* __restrict__ Ahi, const h16* __restrict__ Bhi,
               float* __restrict__ out_f, float scale)
{
    const int bx = blockIdx.x;
    const int by = (int)(gridDim.y - 1 - blockIdx.y);   // heavy tiles first
    const int bz = blockIdx.z;
    if (MODE == 2 && bx > by) return;

    extern __shared__ char smem[];
    const uint32_t sbase = smem_u32(smem);

    const int tid    = threadIdx.x;
    const int wid    = tid >> 5;
    const int lane   = tid & 31;
    const int warp_m = wid & 1;
    const int warp_n = wid >> 1;

    const size_t boff = (size_t)bz * 2048 * 2048;
    const h16* Ah = Ahi + boff + (size_t)(by * 128) * 2048;
    const h16* Bh = Bhi + boff + (size_t)(bx * 128) * 2048;

    const int nk = (MODE == 3) ? (by + 1) * 4 : 64;

    float acc[4][8][4] = {};
    gemm_mainloop(Ah, Bh, sbase, nk, tid, lane, warp_m, warp_n, acc);

    const int tq = lane >> 2;
    const int tr = lane & 3;
    const float sc = (MODE == 2) ? scale : 1.0f;

#pragma unroll
    for (int mt = 0; mt < 4; ++mt)
#pragma unroll
        for (int nt = 0; nt < 8; ++nt) {
            const int gm = by * 128 + warp_m * 64 + mt * 16 + tq;
            const int gn = bx * 128 + warp_n * 64 + nt * 8 + tr * 2;
#pragma unroll
            for (int h = 0; h < 2; ++h) {
                const size_t o = boff + (size_t)(gm + h * 8) * 2048 + gn;
                *(float2*)(out_f + o) = make_float2(acc[mt][nt][h * 2 + 0] * sc,
                                                    acc[mt][nt][h * 2 + 1] * sc);
            }
        }
}

// ---------------------------------------------------------------------------
// Merged fp32 -> fp16 rounding for all 4 inputs. grid.y selects the tensor.
// ---------------------------------------------------------------------------
__global__ void split_all_kernel(const float* __restrict__ x,
                                 const float* __restrict__ wq,
                                 const float* __restrict__ wk,
                                 const float* __restrict__ wv,
                                 h16* __restrict__ xo, h16* __restrict__ qo,
                                 h16* __restrict__ ko, h16* __restrict__ vo)
{
    const int a = blockIdx.y;
    const float* s = (a == 0) ? x : (a == 1) ? wq : (a == 2) ? wk : wv;
    h16* d        = (a == 0) ? xo : (a == 1) ? qo : (a == 2) ? ko : vo;
    const int n   = (a == 0) ? BATCH * SEQ * EMB : DIM * EMB;

    const int i = (blockIdx.x * blockDim.x + threadIdx.x) * 8;
    if (i >= n) return;
    const float4 p = *(const float4*)(s + i);
    const float4 q = *(const float4*)(s + i + 4);
    __half2 h0 = __floats2half2_rn(p.x, p.y);
    __half2 h1 = __floats2half2_rn(p.z, p.w);
    __half2 h2 = __floats2half2_rn(q.x, q.y);
    __half2 h3 = __floats2half2_rn(q.z, q.w);
    uint4 o;
    o.x = *(uint32_t*)&h0; o.y = *(uint32_t*)&h1;
    o.z = *(uint32_t*)&h2; o.w = *(uint32_t*)&h3;
    *(uint4*)(d + i) = o;
}

// ---------------------------------------------------------------------------
// Causal softmax: fp32 scores (k<=q valid) -> attn fp16. Longest rows first.
// ---------------------------------------------------------------------------
__global__ void softmax_kernel(const float* __restrict__ S,
                               h16* __restrict__ Phi)
{
    const int row = (int)(gridDim.x - 1 - blockIdx.x);   // heavy rows first
    const int b = row >> 11;
    const int q = row & 2047;
    const float* sr = S + ((size_t)b * SEQ + q) * SEQ;
    const size_t ob = ((size_t)b * SEQ + q) * SEQ;
    const int len  = q + 1;
    const int klim = ((q >> 7) + 1) << 7;

    __shared__ float buf[SEQ];
    __shared__ float red[8];

    float m = -1e30f;
    const int len4 = len & ~3;
    for (int k = threadIdx.x * 4; k < len4; k += blockDim.x * 4) {
        const float4 v = *(const float4*)(sr + k);
        *(float4*)(buf + k) = v;
        m = fmaxf(m, fmaxf(fmaxf(v.x, v.y), fmaxf(v.z, v.w)));
    }
    for (int k = len4 + threadIdx.x; k < len; k += blockDim.x) {
        const float v = sr[k];
        buf[k] = v;
        m = fmaxf(m, v);
    }
#pragma unroll
    for (int o = 16; o; o >>= 1)
        m = fmaxf(m, __shfl_xor_sync(0xffffffffu, m, o));
    if ((threadIdx.x & 31) == 0) red[threadIdx.x >> 5] = m;
    __syncthreads();
    m = red[0];
#pragma unroll
    for (int w = 1; w < 8; ++w) m = fmaxf(m, red[w]);

    float sum = 0.f;
    for (int k = threadIdx.x; k < len; k += blockDim.x) {
        const float e = __expf(buf[k] - m);
        buf[k] = e;
        sum += e;
    }
#pragma unroll
    for (int o = 16; o; o >>= 1)
        sum += __shfl_xor_sync(0xffffffffu, sum, o);
    __syncthreads();
    if ((threadIdx.x & 31) == 0) red[threadIdx.x >> 5] = sum;
    __syncthreads();
    sum = 0.f;
#pragma unroll
    for (int w = 0; w < 8; ++w) sum += red[w];

    const float inv = 1.0f / sum;

    for (int k = threadIdx.x * 8; k < klim; k += blockDim.x * 8) {
        __half2 h[4];
#pragma unroll
        for (int j = 0; j < 4; ++j) {
            const int k0 = k + j * 2;
            const float a0 = (k0     < len) ? buf[k0]     * inv : 0.f;
            const float a1 = (k0 + 1 < len) ? buf[k0 + 1] * inv : 0.f;
            h[j] = __floats2half2_rn(a0, a1);
        }
        uint4 o;
        o.x = *(uint32_t*)&h[0]; o.y = *(uint32_t*)&h[1];
        o.z = *(uint32_t*)&h[2]; o.w = *(uint32_t*)&h[3];
        *(uint4*)(Phi + ob + k) = o;
    }
}

// ---------------------------------------------------------------------------
extern "C" void kernel_launch(void* const* d_in, const int* in_sizes, int n_in,
                              void* d_out, int out_size)
{
    const float* x  = (const float*)d_in[0];
    const float* Wk = (const float*)d_in[1];
    const float* Wq = (const float*)d_in[2];
    const float* Wv = (const float*)d_in[3];
    float* out = (float*)d_out;

    h16 *xhi, *wqh, *wkh, *wvh;
    h16 *qhi, *khi, *vthi, *phi;
    float* s;
    cudaGetSymbolAddress((void**)&xhi,  g_xhi);
    cudaGetSymbolAddress((void**)&wqh,  g_Wqhi);
    cudaGetSymbolAddress((void**)&wkh,  g_Wkhi);
    cudaGetSymbolAddress((void**)&wvh,  g_Wvhi);
    cudaGetSymbolAddress((void**)&qhi,  g_Qhi);
    cudaGetSymbolAddress((void**)&khi,  g_Khi);
    cudaGetSymbolAddress((void**)&vthi, g_Vthi);
    cudaGetSymbolAddress((void**)&phi,  g_Phi);
    cudaGetSymbolAddress((void**)&s,    g_S);

    cudaFuncSetAttribute((const void*)proj_gemm,    cudaFuncAttributeMaxDynamicSharedMemorySize, SMEM_BYTES);
    cudaFuncSetAttribute((const void*)attn_gemm<2>, cudaFuncAttributeMaxDynamicSharedMemorySize, SMEM_BYTES);
    cudaFuncSetAttribute((const void*)attn_gemm<3>, cudaFuncAttributeMaxDynamicSharedMemorySize, SMEM_BYTES);

    const float inv_scale = 1.0f / sqrtf((float)DIM);

    // Side stream + events (verified graph-capturable in R15).
    cudaStream_t s2;
    cudaStreamCreateWithFlags(&s2, cudaStreamNonBlocking);
    cudaEvent_t eSplit, eV;
    cudaEventCreateWithFlags(&eSplit, cudaEventDisableTiming);
    cudaEventCreateWithFlags(&eV,     cudaEventDisableTiming);

    {
        dim3 gs((BATCH * SEQ * EMB / 8 + 255) / 256, 4);
        split_all_kernel<<<gs, 256>>>(x, Wq, Wk, Wv, xhi, wqh, wkh, wvh);
    }
    cudaEventRecord(eSplit, 0);
    cudaStreamWaitEvent(s2, eSplit, 0);

    dim3 blk(128);

    // V projection on the side stream (independent of scores/softmax)
    dim3 gv(DIM / 128, (BATCH * SEQ) / 128, 1);
    proj_gemm<<<gv, blk, SMEM_BYTES, s2>>>(xhi, wqh, wkh, wvh, qhi, khi, vthi, 2);

    // Q + K projections on the main stream
    dim3 gqk(DIM / 128, (BATCH * SEQ) / 128, 2);
    proj_gemm<<<gqk, blk, SMEM_BYTES>>>(xhi, wqh, wkh, wvh, qhi, khi, vthi, 0);

    dim3 gattn(SEQ / 128, SEQ / 128, BATCH);            // 16 x 16 x 4
    attn_gemm<2><<<gattn, blk, SMEM_BYTES>>>(qhi, khi, s, inv_scale);

    softmax_kernel<<<BATCH * SEQ, 256>>>(s, phi);

    // AV needs softmax (stream order) AND V^T (event join)
    cudaEventRecord(eV, s2);
    cudaStreamWaitEvent(0, eV, 0);
    attn_gemm<3><<<gattn, blk, SMEM_BYTES>>>(phi, vthi, out, 0.f);
}